// round 16
// baseline (speedup 1.0000x reference)
#include <cuda_runtime.h>
#include <cuda_fp16.h>
#include <cstdint>

// ---------------- problem constants ----------------
#define SEQ   4096
#define HD    64
#define NH    4
#define BM    64           // s rows per CTA
#define BN    64           // t cols per iteration
#define NTH   256
#define ITERS (SEQ/BN)     // 64

// smem strides: rows are 272B (136 halves; 68 words ≡ 4 mod 32 banks)
#define SQH 136            // Qs/Ks/Vs row stride (halves)
#define SPH 72             // Ps row stride (halves)

// smem byte offsets
#define QS_OFF 0
#define KS_OFF (QS_OFF + BM*SQH*2)        // 17408
#define VS_OFF (KS_OFF + 2*BN*SQH*2)      // 52224
#define PS_OFF (VS_OFF + 2*BN*SQH*2)      // 87040
#define PSBUF  (BM*SPH*2)                 // 9216
#define SMEM_BYTES (PS_OFF + 2*PSBUF)     // 105472
#define TBUF_BYTES (BN*SQH*2)             // 17408

// ---------------- device scratch ----------------
__device__ unsigned g_mask_bits[SEQ * (SEQ / 32)];     // 2 MB packed mask
__device__ float    g_v1sum[NH * HD];                  // sum_t V[1,h,t,d]
__device__ __half   g_kh[NH * SEQ * 128];              // [h][t][k0|k1] fp16
__device__ __half   g_vh[NH * SEQ * 128];              // [h][t][v0|v1] fp16

// ---------------- helpers ----------------
__device__ __forceinline__ float tanh_fast(float x) {
    float y; asm("tanh.approx.f32 %0, %1;" : "=f"(y) : "f"(x)); return y;
}
// Q pre-scaled by 0.0625: p = 0.5 + 0.5*tanh(delta_scaled)
__device__ __forceinline__ float sigp(float d) {
    return fmaf(tanh_fast(d), 0.5f, 0.5f);
}
__device__ __forceinline__ uint32_t f22u(float a, float b) {
    __half2 h = __floats2half2_rn(a, b);
    return *(uint32_t*)&h;
}
__device__ __forceinline__ uint32_t smem_u32(const void* p) {
    uint32_t a;
    asm("{ .reg .u64 t; cvta.to.shared.u64 t, %1; cvt.u32.u64 %0, t; }" : "=r"(a) : "l"(p));
    return a;
}

#define CP_ASYNC16(dst, src) \
    asm volatile("cp.async.cg.shared.global [%0], [%1], 16;" :: "r"(dst), "l"(src) : "memory")
#define CP_COMMIT() asm volatile("cp.async.commit_group;" ::: "memory")
#define CP_WAIT0()  asm volatile("cp.async.wait_group 0;" ::: "memory")
#define CP_WAIT1()  asm volatile("cp.async.wait_group 1;" ::: "memory")

#define LDSM_X4(r, addr) asm volatile( \
    "ldmatrix.sync.aligned.m8n8.x4.shared.b16 {%0,%1,%2,%3}, [%4];" \
    : "=r"((r)[0]), "=r"((r)[1]), "=r"((r)[2]), "=r"((r)[3]) : "r"(addr))

#define LDSM_X4T(r, addr) asm volatile( \
    "ldmatrix.sync.aligned.m8n8.x4.trans.shared.b16 {%0,%1,%2,%3}, [%4];" \
    : "=r"((r)[0]), "=r"((r)[1]), "=r"((r)[2]), "=r"((r)[3]) : "r"(addr))

#define MMA16816(d, a, b0, b1) asm volatile( \
    "mma.sync.aligned.m16n8k16.row.col.f32.f16.f16.f32 " \
    "{%0,%1,%2,%3}, {%4,%5,%6,%7}, {%8,%9}, {%0,%1,%2,%3};" \
    : "+f"((d)[0]), "+f"((d)[1]), "+f"((d)[2]), "+f"((d)[3]) \
    : "r"((a)[0]), "r"((a)[1]), "r"((a)[2]), "r"((a)[3]), "r"(b0), "r"(b1))

// ---------------- fused prologue kernel ----------------
// blocks [0,2048): pack mask ; [2048,3072): convert K/V ; [3072,3076): v1sum
__global__ void prologue_kernel(const int* __restrict__ mask,
                                const float* __restrict__ k,
                                const float* __restrict__ v) {
    const int bx = blockIdx.x;
    const int tid = threadIdx.x;
    if (bx < 2048) {
        int w = bx * 256 + tid;                     // 0 .. SEQ*128-1
        const int4* src = (const int4*)(mask + (size_t)w * 32);
        unsigned bits = 0;
        #pragma unroll
        for (int g = 0; g < 8; g++) {
            int4 m4 = src[g];
            bits |= (m4.x != 0 ? 1u : 0u) << (g * 4 + 0);
            bits |= (m4.y != 0 ? 1u : 0u) << (g * 4 + 1);
            bits |= (m4.z != 0 ? 1u : 0u) << (g * 4 + 2);
            bits |= (m4.w != 0 ? 1u : 0u) << (g * 4 + 3);
        }
        g_mask_bits[w] = bits;
    } else if (bx < 3072) {
        int i = (bx - 2048) * 256 + tid;            // 0 .. NH*SEQ*16-1
        int c   = i & 15;
        int row = i >> 4;
        int b   = c >> 3;
        int d0  = (c & 7) * 8;
        size_t g = ((size_t)b * NH * SEQ + row) * HD + d0;
        float4 a0 = *(const float4*)(k + g);
        float4 a1 = *(const float4*)(k + g + 4);
        uint4 o;
        o.x = f22u(a0.x, a0.y); o.y = f22u(a0.z, a0.w);
        o.z = f22u(a1.x, a1.y); o.w = f22u(a1.z, a1.w);
        *(uint4*)(g_kh + (size_t)row * 128 + c * 8) = o;
        float4 b0v = *(const float4*)(v + g);
        float4 b1v = *(const float4*)(v + g + 4);
        uint4 p;
        p.x = f22u(b0v.x, b0v.y); p.y = f22u(b0v.z, b0v.w);
        p.z = f22u(b1v.x, b1v.y); p.w = f22u(b1v.z, b1v.w);
        *(uint4*)(g_vh + (size_t)row * 128 + c * 8) = p;
    } else {
        __shared__ float red[256];
        int h = bx - 3072;
        int d = tid & 63;
        int part = tid >> 6;
        float s = 0.f;
        for (int t = part; t < SEQ; t += 4)
            s += v[(((size_t)NH + h) * SEQ + t) * HD + d];   // b=1
        red[tid] = s;
        __syncthreads();
        if (part == 0)
            g_v1sum[h * HD + d] = red[d] + red[64 + d] + red[128 + d] + red[192 + d];
    }
}

// ---------------- main kernel ----------------
__global__ __launch_bounds__(NTH, 2)
void sdpa_mma_kernel(const float* __restrict__ q,
                     float* __restrict__ out,
                     float* __restrict__ attn)
{
    extern __shared__ char sm[];
    const uint32_t smb = smem_u32(sm);

    const int h   = blockIdx.y;
    const int s0  = blockIdx.x * BM;
    const int tid = threadIdx.x;
    const int w    = tid >> 5;
    const int lane = tid & 31;
    const int gr  = lane >> 2;     // group id (0..7)
    const int ct  = lane & 3;      // thread-in-group
    const int wm  = w & 1;         // warp m-group (32 rows) 0..1
    const int wn  = w >> 1;        // warp n-group 0..3

    const size_t hseq = (size_t)h * SEQ;

    // ---- cp.async staging identity: 4 chunks per tile per thread ----
    const int srow0 = tid >> 4;           // 0..15
    const int sc16  = tid & 15;           // chunk col
    const uint32_t dstb = (uint32_t)(srow0 * (SQH*2) + sc16 * 16);
    const size_t   srcb = ((size_t)srow0) * 128 + sc16 * 8;
    const __half* kp0 = g_kh + hseq * 128;
    const __half* vp0 = g_vh + hseq * 128;

    // ---- stage Q (once): A = [q0 | -q1] * 0.0625, fp16 (scale exact) ----
    {
        const int pr0 = tid >> 5;      // 0..7
        const int pc4 = tid & 31;
        const int pb  = pc4 >> 4;
        const int pd4 = pc4 & 15;
        const size_t bh = ((size_t)pb * NH + h) * SEQ;
        const float sgn = pb ? -0.0625f : 0.0625f;
        #pragma unroll
        for (int j = 0; j < 8; j++) {
            int row = pr0 + 8 * j;
            float4 val = *(const float4*)(q + (bh + s0 + row) * HD + pd4 * 4);
            uint2 o;
            o.x = f22u(sgn * val.x, sgn * val.y);
            o.y = f22u(sgn * val.z, sgn * val.w);
            *(uint2*)(sm + QS_OFF + row * (SQH*2) + pc4 * 8) = o;
        }
    }

    // ---- issue cp.async for tiles 0 and 1 (two groups in flight) ----
    #pragma unroll
    for (int j = 0; j < 4; j++) {
        uint32_t d = dstb + j * 16 * (SQH*2);
        size_t   s = srcb + (size_t)j * 16 * 128;
        CP_ASYNC16(smb + KS_OFF + d, kp0 + s);
        CP_ASYNC16(smb + VS_OFF + d, vp0 + s);
    }
    CP_COMMIT();
    #pragma unroll
    for (int j = 0; j < 4; j++) {
        uint32_t d = dstb + j * 16 * (SQH*2) + TBUF_BYTES;
        size_t   s = srcb + (size_t)j * 16 * 128 + (size_t)BN * 128;
        CP_ASYNC16(smb + KS_OFF + d, kp0 + s);
        CP_ASYNC16(smb + VS_OFF + d, vp0 + s);
    }
    CP_COMMIT();

    // ---- ldmatrix lane-address bases (byte offsets) ----
    const uint32_t qa = smb + QS_OFF + (wm*32 + (lane & 15)) * (SQH*2) + (lane >> 4) * 16;
    const uint32_t kbofs = (uint32_t)((wn*16 + (lane & 7) + (lane >> 4) * 8) * (SQH*2)
                        + ((lane >> 3) & 1) * 16);
    const uint32_t pofs = (uint32_t)((wm*32 + (lane & 15)) * (SPH*2) + (lane >> 4) * 16);
    const uint32_t vbrow = ((lane & 7) + ((lane >> 3) & 1) * 8) * (SQH*2);
    const uint32_t vbcol = (wn*32 + (lane >> 4) * 8) * 2;

    // ---- persistent O accumulators: warp tile 32 rows x 32 cols ----
    float oc[2][4][4];
    #pragma unroll
    for (int mt = 0; mt < 2; mt++)
        #pragma unroll
        for (int nt = 0; nt < 4; nt++)
            #pragma unroll
            for (int u = 0; u < 4; u++) oc[mt][nt][u] = 0.f;

    float* attn1 = attn + (size_t)NH * SEQ * SEQ;
    const int erow0 = s0 + wm*32 + gr;               // + mt*16 + 8u
    const int ecol0 = wn*16 + 2*ct;                  // + nt*8 ; + t0

    float sc[2][2][4];   // Delta fragments for the "current+1" tile

    // ================= pipeline prologue: MMA1(0) + epilogue(0) ============
    CP_WAIT1();          // tile 0 arrived
    __syncthreads();     // Qs + K/V(0) visible

    {
        #pragma unroll
        for (int mt = 0; mt < 2; mt++)
            #pragma unroll
            for (int nt = 0; nt < 2; nt++)
                #pragma unroll
                for (int u = 0; u < 4; u++) sc[mt][nt][u] = 0.f;
        const uint32_t kb = smb + KS_OFF + 0 + kbofs;
        #pragma unroll
        for (int kk = 0; kk < 8; kk++) {
            uint32_t a0[4], a1[4], b[4];
            LDSM_X4(a0, qa + kk * 32);
            LDSM_X4(a1, qa + kk * 32 + 16 * (SQH*2));
            LDSM_X4(b,  kb + kk * 32);
            MMA16816(sc[0][0], a0, b[0], b[1]);
            MMA16816(sc[0][1], a0, b[2], b[3]);
            MMA16816(sc[1][0], a1, b[0], b[1]);
            MMA16816(sc[1][1], a1, b[2], b[3]);
        }
        // epilogue(0): mask + sigmoid ; Ps[0] ; attn(t0=0)
        #pragma unroll
        for (int mt = 0; mt < 2; mt++) {
            #pragma unroll
            for (int u = 0; u < 2; u++) {
                int rowl = wm*32 + mt*16 + gr + 8*u;
                unsigned m = g_mask_bits[(size_t)(s0 + rowl) * 128 + (wn >> 1)];
                size_t ar = (hseq + s0 + rowl) * SEQ + ecol0;
                #pragma unroll
                for (int nt = 0; nt < 2; nt++) {
                    int bitb = (wn & 1) * 16 + nt * 8 + 2 * ct;
                    float x0 = ((m >> bitb) & 1)       ? 0.f : sc[mt][nt][2*u + 0];
                    float x1 = ((m >> (bitb + 1)) & 1) ? 0.f : sc[mt][nt][2*u + 1];
                    float p0 = sigp(x0);
                    float p1 = sigp(x1);
                    *(uint32_t*)(sm + PS_OFF + rowl * (SPH*2)
                                 + (wn*16 + nt*8 + 2*ct) * 2) = f22u(p0, p1);
                    __stcs((float2*)(attn  + ar + nt*8), make_float2(p0, p1));
                    __stcs((float2*)(attn1 + ar + nt*8),
                           make_float2(1.f - p0, 1.f - p1));
                }
            }
        }
    }

    // ================= main pipelined loop =================
    for (int it = 0; it < ITERS; ++it) {
        const uint32_t bufc = (it & 1) * TBUF_BYTES;        // V/Ps for MMA2(it)
        const uint32_t bufn = ((it + 1) & 1) * TBUF_BYTES;  // K for MMA1(it+1)

        CP_WAIT0();
        __syncthreads();   // BAR A: Ps[it&1] + K/V(it+1) visible

        const uint32_t pab = smb + PS_OFF + (it & 1) * PSBUF + pofs;
        const uint32_t vb  = smb + VS_OFF + bufc + vbrow + vbcol;

        if (it + 1 < ITERS) {
            // mask prefetch for tile it+1 (hidden behind MMA window)
            unsigned mw[2][2];
            #pragma unroll
            for (int mt = 0; mt < 2; mt++)
                #pragma unroll
                for (int u = 0; u < 2; u++)
                    mw[mt][u] = g_mask_bits[(size_t)(erow0 + mt*16 + 8*u) * 128
                                            + (it + 1) * 2 + (wn >> 1)];

            #pragma unroll
            for (int mt = 0; mt < 2; mt++)
                #pragma unroll
                for (int nt = 0; nt < 2; nt++)
                    #pragma unroll
                    for (int u = 0; u < 4; u++) sc[mt][nt][u] = 0.f;

            // ---- interleaved MMA1(it+1) + MMA2(it) ----
            const uint32_t kb = smb + KS_OFF + bufn + kbofs;
            #pragma unroll
            for (int kk = 0; kk < 8; kk++) {
                uint32_t a0[4], a1[4], b[4];
                LDSM_X4(a0, qa + kk * 32);
                LDSM_X4(a1, qa + kk * 32 + 16 * (SQH*2));
                LDSM_X4(b,  kb + kk * 32);
                MMA16816(sc[0][0], a0, b[0], b[1]);
                MMA16816(sc[0][1], a0, b[2], b[3]);
                MMA16816(sc[1][0], a1, b[0], b[1]);
                MMA16816(sc[1][1], a1, b[2], b[3]);
                if (kk < 4) {
                    uint32_t p0[4], p1[4], bA[4], bB[4];
                    LDSM_X4(p0, pab + kk * 32);
                    LDSM_X4(p1, pab + kk * 32 + 16 * (SPH*2));
                    uint32_t vaddr = vb + (uint32_t)kk * 16 * (SQH*2);
                    LDSM_X4T(bA, vaddr);
                    LDSM_X4T(bB, vaddr + 32);
                    MMA16816(oc[0][0], p0, bA[0], bA[1]);
                    MMA16816(oc[0][1], p0, bA[2], bA[3]);
                    MMA16816(oc[0][2], p0, bB[0], bB[1]);
                    MMA16816(oc[0][3], p0, bB[2], bB[3]);
                    MMA16816(oc[1][0], p1, bA[0], bA[1]);
                    MMA16816(oc[1][1], p1, bA[2], bA[3]);
                    MMA16816(oc[1][2], p1, bB[0], bB[1]);
                    MMA16816(oc[1][3], p1, bB[2], bB[3]);
                }
            }

            __syncthreads();   // BAR B: V[it&1] free for overwrite

            // ---- cp.async tile it+2 into buffer (it&1) ----
            if (it + 2 < ITERS) {
                const __half* kp = g_kh + (hseq + (size_t)(it + 2) * BN) * 128;
                const __half* vp = g_vh + (hseq + (size_t)(it + 2) * BN) * 128;
                #pragma unroll
                for (int j = 0; j < 4; j++) {
                    uint32_t d = dstb + j * 16 * (SQH*2) + bufc;
                    size_t   s = srcb + (size_t)j * 16 * 128;
                    CP_ASYNC16(smb + KS_OFF + d, kp + s);
                    CP_ASYNC16(smb + VS_OFF + d, vp + s);
                }
                CP_COMMIT();
            }

            // ---- epilogue(it+1): sigmoid -> Ps[(it+1)&1] + attn stores ----
            const int t1 = (it + 1) * BN;
            #pragma unroll
            for (int mt = 0; mt < 2; mt++) {
                #pragma unroll
                for (int u = 0; u < 2; u++) {
                    int rowl = wm*32 + mt*16 + gr + 8*u;
                    size_t ar = (hseq + s0 + rowl) * SEQ + t1 + ecol0;
                    unsigned m = mw[mt][u];
                    #pragma unroll
                    for (int nt = 0; nt < 2; nt++) {
                        int bitb = (wn & 1) * 16 + nt * 8 + 2 * ct;
                        float x0 = ((m >> bitb) & 1)       ? 0.f : sc[mt][nt][2*u + 0];
                        float x1 = ((m >> (bitb + 1)) & 1) ? 0.f : sc[mt][nt][2*u + 1];
                        float p0 = sigp(x0);
                        float p1 = sigp(x1);
                        *(uint32_t*)(sm + PS_OFF + ((it + 1) & 1) * PSBUF
                                     + rowl * (SPH*2)
                                     + (wn*16 + nt*8 + 2*ct) * 2) = f22u(p0, p1);
                        __stcs((float2*)(attn  + ar + nt*8), make_float2(p0, p1));
                        __stcs((float2*)(attn1 + ar + nt*8),
                               make_float2(1.f - p0, 1.f - p1));
                    }
                }
            }
        } else {
            // last iteration: only MMA2(63)
            #pragma unroll
            for (int kk = 0; kk < 4; kk++) {
                uint32_t p0[4], p1[4], bA[4], bB[4];
                LDSM_X4(p0, pab + kk * 32);
                LDSM_X4(p1, pab + kk * 32 + 16 * (SPH*2));
                uint32_t vaddr = vb + (uint32_t)kk * 16 * (SQH*2);
                LDSM_X4T(bA, vaddr);
                LDSM_X4T(bB, vaddr + 32);
                MMA16816(oc[0][0], p0, bA[0], bA[1]);
                MMA16816(oc[0][1], p0, bA[2], bA[3]);
                MMA16816(oc[0][2], p0, bB[0], bB[1]);
                MMA16816(oc[0][3], p0, bB[2], bB[3]);
                MMA16816(oc[1][0], p1, bA[0], bA[1]);
                MMA16816(oc[1][1], p1, bA[2], bA[3]);
                MMA16816(oc[1][2], p1, bB[0], bB[1]);
                MMA16816(oc[1][3], p1, bB[2], bB[3]);
            }
        }
    }

    // ---- final out write: wn 0,1 -> b0 = acc ; wn 2,3 -> b1 = v1sum - acc ----
    const float* vs = g_v1sum + h * HD;
    const int b = wn >> 1;
    #pragma unroll
    for (int mt = 0; mt < 2; mt++) {
        int row = s0 + wm*32 + mt*16 + gr;
        #pragma unroll
        for (int nt = 0; nt < 4; nt++) {
            int n0 = wn*32 + nt*8 + 2*ct;
            int d  = n0 & 63;
            float* c = oc[mt][nt];
            float2 w0, w1;
            if (b == 0) {
                w0 = make_float2(c[0], c[1]);
                w1 = make_float2(c[2], c[3]);
            } else {
                w0 = make_float2(vs[d] - c[0], vs[d + 1] - c[1]);
                w1 = make_float2(vs[d] - c[2], vs[d + 1] - c[3]);
            }
            size_t ob = (((size_t)b * NH + h) * SEQ + row) * HD + d;
            *(float2*)(out + ob)          = w0;
            *(float2*)(out + ob + 8 * HD) = w1;
        }
    }
}

// ---------------- launcher ----------------
extern "C" void kernel_launch(void* const* d_in, const int* in_sizes, int n_in,
                              void* d_out, int out_size)
{
    const float* q    = (const float*)d_in[0];
    const float* k    = (const float*)d_in[1];
    const float* v    = (const float*)d_in[2];
    const int*   mask = (const int*)  d_in[3];

    float* out  = (float*)d_out;
    float* attn = out + (size_t)2 * NH * SEQ * HD;

    prologue_kernel<<<3076, 256>>>(mask, k, v);

    cudaFuncSetAttribute(sdpa_mma_kernel,
                         cudaFuncAttributeMaxDynamicSharedMemorySize, SMEM_BYTES);
    dim3 grid(SEQ / BM, NH);
    sdpa_mma_kernel<<<grid, NTH, SMEM_BYTES>>>(q, out, attn);
}

// round 17
// speedup vs baseline: 1.1617x; 1.1617x over previous
#include <cuda_runtime.h>
#include <cuda_fp16.h>
#include <cstdint>

// ---------------- problem constants ----------------
#define SEQ   4096
#define HD    64
#define NH    4
#define BM    64           // s rows per CTA
#define BN    64           // t cols per iteration
#define NTH   256
#define ITERS (SEQ/BN)     // 64
#define NCTA  (NH * SEQ / BM)   // 256 total CTAs

// smem strides: rows are 272B (136 halves; 68 words ≡ 4 mod 32 banks)
#define SQH 136            // Qs/Ks/Vs row stride (halves)
#define SPH 72             // Ps row stride (halves)

// smem byte offsets
#define QS_OFF 0
#define KS_OFF (QS_OFF + BM*SQH*2)        // 17408
#define VS_OFF (KS_OFF + 2*BN*SQH*2)      // 52224
#define PS_OFF (VS_OFF + 2*BN*SQH*2)      // 87040
#define SMEM_BYTES (PS_OFF + BM*SPH*2)    // 96256
#define TBUF_BYTES (BN*SQH*2)             // 17408

// ---------------- device scratch ----------------
__device__ unsigned g_mask_bits[SEQ * (SEQ / 32)];     // 2 MB packed mask
__device__ float    g_v1part[NH][8][HD];               // v1 partial sums
__device__ __half   g_kh[NH * SEQ * 128];              // [h][t][k0|k1] fp16
__device__ __half   g_vh[NH * SEQ * 128];              // [h][t][v0|v1] fp16
__device__ unsigned long long g_arrive;                // grid barrier (monotonic)

// ---------------- helpers ----------------
__device__ __forceinline__ float tanh_fast(float x) {
    float y; asm("tanh.approx.f32 %0, %1;" : "=f"(y) : "f"(x)); return y;
}
// Q pre-scaled by 0.0625: p = 0.5 + 0.5*tanh(delta_scaled)
__device__ __forceinline__ float sigp(float d) {
    return fmaf(tanh_fast(d), 0.5f, 0.5f);
}
__device__ __forceinline__ uint32_t f22u(float a, float b) {
    __half2 h = __floats2half2_rn(a, b);
    return *(uint32_t*)&h;
}
__device__ __forceinline__ uint32_t smem_u32(const void* p) {
    uint32_t a;
    asm("{ .reg .u64 t; cvta.to.shared.u64 t, %1; cvt.u32.u64 %0, t; }" : "=r"(a) : "l"(p));
    return a;
}

#define CP_ASYNC16(dst, src) \
    asm volatile("cp.async.cg.shared.global [%0], [%1], 16;" :: "r"(dst), "l"(src) : "memory")
#define CP_COMMIT() asm volatile("cp.async.commit_group;" ::: "memory")
#define CP_WAIT0()  asm volatile("cp.async.wait_group 0;" ::: "memory")
#define BAR_SYNC(id) asm volatile("bar.sync %0, 128;" :: "r"(id) : "memory")

#define LDSM_X4(r, addr) asm volatile( \
    "ldmatrix.sync.aligned.m8n8.x4.shared.b16 {%0,%1,%2,%3}, [%4];" \
    : "=r"((r)[0]), "=r"((r)[1]), "=r"((r)[2]), "=r"((r)[3]) : "r"(addr))

#define LDSM_X4T(r, addr) asm volatile( \
    "ldmatrix.sync.aligned.m8n8.x4.trans.shared.b16 {%0,%1,%2,%3}, [%4];" \
    : "=r"((r)[0]), "=r"((r)[1]), "=r"((r)[2]), "=r"((r)[3]) : "r"(addr))

#define MMA16816(d, a, b0, b1) asm volatile( \
    "mma.sync.aligned.m16n8k16.row.col.f32.f16.f16.f32 " \
    "{%0,%1,%2,%3}, {%4,%5,%6,%7}, {%8,%9}, {%0,%1,%2,%3};" \
    : "+f"((d)[0]), "+f"((d)[1]), "+f"((d)[2]), "+f"((d)[3]) \
    : "r"((a)[0]), "r"((a)[1]), "r"((a)[2]), "r"((a)[3]), "r"(b0), "r"(b1))

// ---------------- fused kernel ----------------
__global__ __launch_bounds__(NTH, 2)
void sdpa_fused_kernel(const float* __restrict__ q,
                       const float* __restrict__ k,
                       const float* __restrict__ v,
                       const int*   __restrict__ mask,
                       float* __restrict__ out,
                       float* __restrict__ attn)
{
    extern __shared__ char sm[];
    const uint32_t smb = smem_u32(sm);

    const int h   = blockIdx.y;
    const int s0  = blockIdx.x * BM;
    const int tid = threadIdx.x;
    const int cta = blockIdx.y * gridDim.x + blockIdx.x;   // 0..255
    const int gt  = cta * NTH + tid;                       // 0..65535

    // ================= PHASE 0: distributed prologue =================
    // mask pack: 8 words per thread (SEQ*128 = 524288 = 8*65536)
    #pragma unroll
    for (int j = 0; j < 8; j++) {
        int ww = gt + j * 65536;
        const int4* src = (const int4*)(mask + (size_t)ww * 32);
        unsigned bits = 0;
        #pragma unroll
        for (int g = 0; g < 8; g++) {
            int4 m4 = src[g];
            bits |= (m4.x != 0 ? 1u : 0u) << (g * 4 + 0);
            bits |= (m4.y != 0 ? 1u : 0u) << (g * 4 + 1);
            bits |= (m4.z != 0 ? 1u : 0u) << (g * 4 + 2);
            bits |= (m4.w != 0 ? 1u : 0u) << (g * 4 + 3);
        }
        g_mask_bits[ww] = bits;
    }
    // K/V fp16 convert: 4 chunks per thread (NH*SEQ*16 = 262144 = 4*65536)
    #pragma unroll
    for (int j = 0; j < 4; j++) {
        int i   = gt + j * 65536;
        int c   = i & 15;
        int row = i >> 4;
        int b   = c >> 3;
        int d0  = (c & 7) * 8;
        size_t g = ((size_t)b * NH * SEQ + row) * HD + d0;
        float4 a0 = *(const float4*)(k + g);
        float4 a1 = *(const float4*)(k + g + 4);
        uint4 o;
        o.x = f22u(a0.x, a0.y); o.y = f22u(a0.z, a0.w);
        o.z = f22u(a1.x, a1.y); o.w = f22u(a1.z, a1.w);
        *(uint4*)(g_kh + (size_t)row * 128 + c * 8) = o;
        float4 b0v = *(const float4*)(v + g);
        float4 b1v = *(const float4*)(v + g + 4);
        uint4 p;
        p.x = f22u(b0v.x, b0v.y); p.y = f22u(b0v.z, b0v.w);
        p.z = f22u(b1v.x, b1v.y); p.w = f22u(b1v.z, b1v.w);
        *(uint4*)(g_vh + (size_t)row * 128 + c * 8) = p;
    }
    // v1 partials: CTAs 0..31, fixed-order (deterministic, no FP atomics)
    if (cta < 32) {
        float* red = (float*)sm;            // scratch (pre-Q staging)
        int ph = cta >> 3;                  // head
        int pp = cta & 7;                   // partial index
        int d   = tid & 63;
        int sub = tid >> 6;                 // 0..3
        float s = 0.f;
        int tbeg = pp * 512 + sub * 128;
        for (int t = tbeg; t < tbeg + 128; t++)
            s += v[(((size_t)NH + ph) * SEQ + t) * HD + d];   // b=1
        red[tid] = s;
        __syncthreads();
        if (sub == 0)
            g_v1part[ph][pp][d] = red[d] + red[64 + d] + red[128 + d] + red[192 + d];
    }
    __syncthreads();   // scratch free before Q staging

    // ---- stage Q (independent of phase 0): A = [q0|-q1]*0.0625, fp16 ----
    {
        const int pr0 = tid >> 5;      // 0..7
        const int pc4 = tid & 31;
        const int pb  = pc4 >> 4;
        const int pd4 = pc4 & 15;
        const size_t bh = ((size_t)pb * NH + h) * SEQ;
        const float sgn = pb ? -0.0625f : 0.0625f;
        #pragma unroll
        for (int j = 0; j < 8; j++) {
            int row = pr0 + 8 * j;
            float4 val = *(const float4*)(q + (bh + s0 + row) * HD + pd4 * 4);
            uint2 o;
            o.x = f22u(sgn * val.x, sgn * val.y);
            o.y = f22u(sgn * val.z, sgn * val.w);
            *(uint2*)(sm + QS_OFF + row * (SQH*2) + pc4 * 8) = o;
        }
    }

    // ================= grid barrier (epoch-based, replay-safe) =========
    if (tid == 0) {
        __threadfence();
        unsigned long long old = atomicAdd(&g_arrive, 1ULL);
        unsigned long long target = (old / (unsigned long long)NCTA) * NCTA + NCTA;
        while (*(volatile unsigned long long*)&g_arrive < target)
            __nanosleep(64);
        __threadfence();
    }
    __syncthreads();

    // ================= main attention loop (round-15 structure) ========
    const size_t hseq = (size_t)h * SEQ;
    const int w    = tid >> 5;
    const int lane = tid & 31;
    const int gr  = lane >> 2;
    const int ct  = lane & 3;
    const int wm  = w & 1;
    const int wn  = w >> 1;

    const int srow0 = tid >> 4;
    const int sc16  = tid & 15;
    const uint32_t dstb = (uint32_t)(srow0 * (SQH*2) + sc16 * 16);
    const size_t   srcb = ((size_t)srow0) * 128 + sc16 * 8;

    // ---- issue cp.async for tile 0 ----
    {
        const __half* kp = g_kh + hseq * 128;
        const __half* vp = g_vh + hseq * 128;
        #pragma unroll
        for (int j = 0; j < 4; j++) {
            uint32_t d = dstb + j * 16 * (SQH*2);
            size_t   s = srcb + (size_t)j * 16 * 128;
            CP_ASYNC16(smb + KS_OFF + d, kp + s);
            CP_ASYNC16(smb + VS_OFF + d, vp + s);
        }
        CP_COMMIT();
    }

    const uint32_t qa = smb + QS_OFF + (wm*32 + (lane & 15)) * (SQH*2) + (lane >> 4) * 16;
    const uint32_t kbofs = (uint32_t)((wn*16 + (lane & 7) + (lane >> 4) * 8) * (SQH*2)
                        + ((lane >> 3) & 1) * 16);
    const uint32_t pa = smb + PS_OFF + (wm*32 + (lane & 15)) * (SPH*2) + (lane >> 4) * 16;
    const uint32_t vbrow = ((lane & 7) + ((lane >> 3) & 1) * 8) * (SQH*2);
    const uint32_t vbcol = (wn*32 + (lane >> 4) * 8) * 2;

    float oc[2][4][4];
    #pragma unroll
    for (int mt = 0; mt < 2; mt++)
        #pragma unroll
        for (int nt = 0; nt < 4; nt++)
            #pragma unroll
            for (int u = 0; u < 4; u++) oc[mt][nt][u] = 0.f;

    float* attn1 = attn + (size_t)NH * SEQ * SEQ;
    const int erow0 = s0 + wm*32 + gr;
    const int ecol0 = wn*16 + 2*ct;

    for (int it = 0; it < ITERS; ++it) {
        const int t0  = it * BN;
        const uint32_t buf = (it & 1) * TBUF_BYTES;

        CP_WAIT0();
        __syncthreads();

        if (it + 1 < ITERS) {
            const uint32_t nbuf = ((it + 1) & 1) * TBUF_BYTES;
            const __half* kp = g_kh + (hseq + t0 + BN) * 128;
            const __half* vp = g_vh + (hseq + t0 + BN) * 128;
            #pragma unroll
            for (int j = 0; j < 4; j++) {
                uint32_t d = dstb + j * 16 * (SQH*2);
                size_t   s = srcb + (size_t)j * 16 * 128;
                CP_ASYNC16(smb + KS_OFF + nbuf + d, kp + s);
                CP_ASYNC16(smb + VS_OFF + nbuf + d, vp + s);
            }
            CP_COMMIT();
        }

        // ---- prefetch mask words (hide L2 latency behind MMA1) ----
        unsigned mw[2][2];
        #pragma unroll
        for (int mt = 0; mt < 2; mt++)
            #pragma unroll
            for (int u = 0; u < 2; u++)
                mw[mt][u] = g_mask_bits[(size_t)(erow0 + mt*16 + 8*u) * 128
                                        + it * 2 + (wn >> 1)];

        // ---- MMA1: Delta[64][64] ; warp tile 32x16 ----
        float sc[2][2][4];
        #pragma unroll
        for (int mt = 0; mt < 2; mt++)
            #pragma unroll
            for (int nt = 0; nt < 2; nt++)
                #pragma unroll
                for (int u = 0; u < 4; u++) sc[mt][nt][u] = 0.f;

        const uint32_t kb = smb + KS_OFF + buf + kbofs;
        #pragma unroll
        for (int kk = 0; kk < 8; kk++) {
            uint32_t a0[4], a1[4], b[4];
            LDSM_X4(a0, qa + kk * 32);
            LDSM_X4(a1, qa + kk * 32 + 16 * (SQH*2));
            LDSM_X4(b,  kb + kk * 32);
            MMA16816(sc[0][0], a0, b[0], b[1]);
            MMA16816(sc[0][1], a0, b[2], b[3]);
            MMA16816(sc[1][0], a1, b[0], b[1]);
            MMA16816(sc[1][1], a1, b[2], b[3]);
        }

        // ---- epilogue: mask + tanh-sigmoid ; stage P ; attn from regs ----
        #pragma unroll
        for (int mt = 0; mt < 2; mt++) {
            #pragma unroll
            for (int u = 0; u < 2; u++) {
                int rowl = wm*32 + mt*16 + gr + 8*u;
                size_t ar = (hseq + s0 + rowl) * SEQ + t0 + ecol0;
                unsigned m = mw[mt][u];
                #pragma unroll
                for (int nt = 0; nt < 2; nt++) {
                    int bitb = (wn & 1) * 16 + nt * 8 + 2 * ct;
                    // masked -> delta=0 -> tanh(0)=0 -> p=0.5 exactly
                    float x0 = ((m >> bitb) & 1)       ? 0.f : sc[mt][nt][2*u + 0];
                    float x1 = ((m >> (bitb + 1)) & 1) ? 0.f : sc[mt][nt][2*u + 1];
                    float p0 = sigp(x0);
                    float p1 = sigp(x1);
                    *(uint32_t*)(sm + PS_OFF + rowl * (SPH*2)
                                 + (wn*16 + nt*8 + 2*ct) * 2) = f22u(p0, p1);
                    __stcs((float2*)(attn  + ar + nt*8), make_float2(p0, p1));
                    __stcs((float2*)(attn1 + ar + nt*8),
                           make_float2(1.f - p0, 1.f - p1));
                }
            }
        }
        BAR_SYNC(1 + wm);   // per-m-half barrier

        // ---- MMA2: O[64][128] += P0 * [V0|V1] ; warp tile 32x32 ----
        #pragma unroll
        for (int kk = 0; kk < 4; kk++) {
            uint32_t a0[4], a1[4], bA[4], bB[4];
            LDSM_X4(a0, pa + kk * 32);
            LDSM_X4(a1, pa + kk * 32 + 16 * (SPH*2));
            uint32_t vaddr = smb + VS_OFF + buf + vbrow + vbcol + (uint32_t)kk * 16 * (SQH*2);
            LDSM_X4T(bA, vaddr);
            LDSM_X4T(bB, vaddr + 32);
            MMA16816(oc[0][0], a0, bA[0], bA[1]);
            MMA16816(oc[0][1], a0, bA[2], bA[3]);
            MMA16816(oc[0][2], a0, bB[0], bB[1]);
            MMA16816(oc[0][3], a0, bB[2], bB[3]);
            MMA16816(oc[1][0], a1, bA[0], bA[1]);
            MMA16816(oc[1][1], a1, bA[2], bA[3]);
            MMA16816(oc[1][2], a1, bB[0], bB[1]);
            MMA16816(oc[1][3], a1, bB[2], bB[3]);
        }
    }

    // ---- finalize v1sum into smem (Ps region is dead now) ----
    __syncthreads();
    float* vss = (float*)(sm + PS_OFF);
    if (tid < 64) {
        float s = 0.f;
        #pragma unroll
        for (int p = 0; p < 8; p++) s += g_v1part[h][p][tid];
        vss[tid] = s;
    }
    __syncthreads();

    // ---- final out write: wn 0,1 -> b0 = acc ; wn 2,3 -> b1 = v1sum - acc ----
    const int b = wn >> 1;
    #pragma unroll
    for (int mt = 0; mt < 2; mt++) {
        int row = s0 + wm*32 + mt*16 + gr;
        #pragma unroll
        for (int nt = 0; nt < 4; nt++) {
            int n0 = wn*32 + nt*8 + 2*ct;
            int d  = n0 & 63;
            float* c = oc[mt][nt];
            float2 w0, w1;
            if (b == 0) {
                w0 = make_float2(c[0], c[1]);
                w1 = make_float2(c[2], c[3]);
            } else {
                w0 = make_float2(vss[d] - c[0], vss[d + 1] - c[1]);
                w1 = make_float2(vss[d] - c[2], vss[d + 1] - c[3]);
            }
            size_t ob = (((size_t)b * NH + h) * SEQ + row) * HD + d;
            *(float2*)(out + ob)          = w0;
            *(float2*)(out + ob + 8 * HD) = w1;
        }
    }
}

// ---------------- launcher ----------------
extern "C" void kernel_launch(void* const* d_in, const int* in_sizes, int n_in,
                              void* d_out, int out_size)
{
    const float* q    = (const float*)d_in[0];
    const float* k    = (const float*)d_in[1];
    const float* v    = (const float*)d_in[2];
    const int*   mask = (const int*)  d_in[3];

    float* out  = (float*)d_out;
    float* attn = out + (size_t)2 * NH * SEQ * HD;

    cudaFuncSetAttribute(sdpa_fused_kernel,
                         cudaFuncAttributeMaxDynamicSharedMemorySize, SMEM_BYTES);
    dim3 grid(SEQ / BM, NH);
    sdpa_fused_kernel<<<grid, NTH, SMEM_BYTES>>>(q, k, v, mask, out, attn);
}